// round 16
// baseline (speedup 1.0000x reference)
#include <cuda_runtime.h>
#include <cuda_bf16.h>
#include <cstdint>

// Tree: DIM=3, FBITS=8, K=4, DEPTH=10. POS[t]=(4^t-1)/3 = 0x55555 >> (20-2t).
// Identity (verified since R4, rel_err ~3e-8): with full 30-bit reversal,
//   X_rev = sum_t rev3(j_t) << 3t; c0=X&1023, c1=(X>>10)&1023, c2=X>>20.
//
// R15: levels 0..6 all have warp-uniform node (32 consecutive n9 share n9>>6).
// Lane l (l&7 = L) loads level L's flag and computes its rev3-pack via the
// register nibble LUT; lanes 0..5 contribute 3-bit fields to a single
// REDUX.OR (warp-uniform prefix, bits 0..17); level 6's pack is broadcast
// with one shfl and each thread extracts its own rank. Levels 7..9 stay
// per-thread (3 LDG + 3 lookups).
// Nibble LUT (proven since R12):
//   lanes  0..15 : pack of low  nibble, fields = rev3(b)   in {0,4,2,6}
//   lanes 16..31 : pack of high nibble, fields = rev3(b+4) = rev3(b)|1
//   pack(f) = lo(f&15) | hi(f>>4) << 3*popc(f&15)

#define BLOCK   512
#define NBLOCKS 512      // 262144 level-9 nodes

__device__ __forceinline__ unsigned lut_lookup(unsigned pk, unsigned f)
{
    unsigned lo = (unsigned)__shfl_sync(0xffffffffu, (int)pk, (int)(f & 15u));
    unsigned hi = (unsigned)__shfl_sync(0xffffffffu, (int)pk, (int)(16u + (f >> 4)));
    return lo | (hi << (3u * (unsigned)__popc(f & 15u)));
}

__global__ void __launch_bounds__(BLOCK)
nbit_decode_kernel(const int* __restrict__ flags,
                   const float* __restrict__ offset,
                   const float* __restrict__ scale,
                   float* __restrict__ out)
{
    const unsigned n9   = blockIdx.x * BLOCK + threadIdx.x;
    const unsigned lane = threadIdx.x & 31u;

    // ---- Per-thread flag loads, levels 7..9 (issued up front) ----
    const unsigned fl7 = (unsigned)__ldg(&flags[5461  + (int)(n9 >> 4)])  & 255u;
    const unsigned fl8 = (unsigned)__ldg(&flags[21845 + (int)(n9 >> 2)])  & 255u;
    const unsigned fl9 = (unsigned)__ldg(&flags[87381 + (int)n9])         & 255u;

    // ---- Lane-parallel load for levels 0..6: lane handles L = lane&7 ----
    // flag index = (4^L-1)/3 + (n9 >> (18-2L));  (L=7 duplicates L=7? no:
    // lane&7==7 loads level 7's address -> in-bounds, result unused)
    const unsigned L    = lane & 7u;
    const unsigned sh   = 2u * L;
    const unsigned fidx = (0x55555u >> (20u - sh)) + (n9 >> (18u - sh));
    const unsigned fpre = (unsigned)__ldg(&flags[(int)fidx]) & 255u;

    const float s0 = __ldg(&scale[0]),  s1 = __ldg(&scale[1]),  s2 = __ldg(&scale[2]);
    const float o0 = __ldg(&offset[0]), o1 = __ldg(&offset[1]), o2 = __ldg(&offset[2]);

    // ---- Register nibble LUT ----
    const unsigned nib = lane & 15u;
    const unsigned add = (lane >> 4) & 1u;   // high nibble: rev3(b+4)=rev3(b)|1
    unsigned pk = 0, rank = 0;
    if (nib & 1u) { pk |= (0u + add) << (3u * rank); ++rank; }
    if (nib & 2u) { pk |= (4u + add) << (3u * rank); ++rank; }
    if (nib & 4u) { pk |= (2u + add) << (3u * rank); ++rank; }
    if (nib & 8u) { pk |= (6u + add) << (3u * rank);         }

    // ---- One lookup per lane covers levels 0..6 for the whole warp ----
    const unsigned mypack = lut_lookup(pk, fpre);

    // Levels 0..5: rank is warp-uniform ((n9>>(16-2L))&3, same for all 32 n9).
    unsigned contrib = ((mypack >> (3u * ((n9 >> (16u - sh)) & 3u))) & 7u) << (3u * L);
    contrib = (L < 6u) ? contrib : 0u;
    const unsigned pre = __reduce_or_sync(0xffffffffu, contrib);   // bits 0..17

    // Level 6: node warp-uniform, rank per-thread -> broadcast lane 6's pack.
    const unsigned p6 = (unsigned)__shfl_sync(0xffffffffu, (int)mypack, 6);
    const unsigned a6 = ((p6 >> (3u * ((n9 >> 4) & 3u))) & 7u) << 18;

    // ---- Levels 7..8 per-thread ----
    const unsigned a7 = ((lut_lookup(pk, fl7) >> (3u * ((n9 >> 2) & 3u))) & 7u) << 21;
    const unsigned a8 = ((lut_lookup(pk, fl8) >> (3u * ( n9       & 3u))) & 7u) << 24;
    const unsigned p9 = lut_lookup(pk, fl9);     // all 4 leaf contributions

    const unsigned acc = pre | a6 | a7 | a8;

    // c0, c1 shared by the 4 leaves; c2 varies only in its top 3 bits.
    const float v0    = (float)(acc & 1023u)         * s0 + o0;
    const float v1    = (float)((acc >> 10) & 1023u) * s1 + o1;
    const float fbase = (float)((acc >> 20) & 127u)  * s2 + o2;
    const float s2h   = s2 * 128.0f;

    const float vc0 = (float)( p9        & 7u) * s2h + fbase;
    const float vc1 = (float)((p9 >> 3)  & 7u) * s2h + fbase;
    const float vc2 = (float)((p9 >> 6)  & 7u) * s2h + fbase;
    const float vc3 = (float)((p9 >> 9)  & 7u) * s2h + fbase;

    // 12 consecutive floats (48B, 16B-aligned): 3 streaming STG.128.
    float4* o4 = reinterpret_cast<float4*>(out + (size_t)n9 * 12u);
    __stcs(o4 + 0, make_float4(v0,  v1,  vc0, v0));
    __stcs(o4 + 1, make_float4(v1,  vc1, v0,  v1));
    __stcs(o4 + 2, make_float4(vc2, v0,  v1,  vc3));
}

extern "C" void kernel_launch(void* const* d_in, const int* in_sizes, int n_in,
                              void* d_out, int out_size)
{
    const int*   flags  = (const int*)  d_in[0];
    const float* offset = (const float*)d_in[1];
    const float* scale  = (const float*)d_in[2];
    if (n_in == 3 && in_sizes[0] == 3) {   // defensive input-order handling
        int fi = (in_sizes[1] > 3) ? 1 : 2;
        flags = (const int*)d_in[fi];
        int s1 = -1, s2 = -1;
        for (int i = 0; i < 3; ++i) {
            if (i == fi) continue;
            if (s1 < 0) s1 = i; else s2 = i;
        }
        offset = (const float*)d_in[s1];
        scale  = (const float*)d_in[s2];
    }

    nbit_decode_kernel<<<NBLOCKS, BLOCK>>>(flags, offset, scale, (float*)d_out);
}

// round 17
// speedup vs baseline: 1.1290x; 1.1290x over previous
#include <cuda_runtime.h>
#include <cuda_bf16.h>
#include <cstdint>

// Tree: DIM=3, FBITS=8, K=4, DEPTH=10. POS[t]=(4^t-1)/3.
// Identity (verified since R4, rel_err ~3e-8): with full 30-bit reversal,
//   X_rev = sum_t rev3(j_t) << 3t; c0=X&1023, c1=(X>>10)&1023, c2=X>>20.
//
// R16 = R12 (best measured: 7.33us kernel) with MIO-op trims only:
//   - vectorized scale/offset loads (6 LDG -> 4)
//   - redundant &255 masks removed (flags < 256 by construction)
//   - unique-address fl9 load issued first
// 1 thread = level-9 node (4 leaves). No smem, no barrier.
// Byte -> packed rev3(set-bit-position) lookup via warp-register LUT:
//   lanes  0..15 : pack of low  nibble, fields = rev3(b)   in {0,4,2,6}
//   lanes 16..31 : pack of high nibble, fields = rev3(b+4) = rev3(b)|1
//   pack(f) = lo(f&15) | hi(f>>4) << 3*popc(f&15)

#define BLOCK   256
#define NBLOCKS 1024     // 262144 level-9 nodes

__device__ __forceinline__ unsigned lut_lookup(unsigned pk, unsigned f)
{
    unsigned lo = (unsigned)__shfl_sync(0xffffffffu, (int)pk, (int)(f & 15u));
    unsigned hi = (unsigned)__shfl_sync(0xffffffffu, (int)pk, (int)(16u + (f >> 4)));
    return lo | (hi << (3u * (unsigned)__popc(f & 15u)));
}

__global__ void __launch_bounds__(BLOCK)
nbit_decode_kernel(const int* __restrict__ flags,
                   const float* __restrict__ offset,
                   const float* __restrict__ scale,
                   float* __restrict__ out)
{
    const unsigned n9 = blockIdx.x * BLOCK + threadIdx.x;

    // ---- Issue all global loads up front; unique-address fl9 first ----
    const unsigned fl9 = (unsigned)__ldg(&flags[87381 + (int)n9]);
    const unsigned fl8 = (unsigned)__ldg(&flags[21845 + (int)(n9 >> 2)]);
    const unsigned fl7 = (unsigned)__ldg(&flags[5461  + (int)(n9 >> 4)]);
    const unsigned fl6 = (unsigned)__ldg(&flags[1365  + (int)(n9 >> 6)]);
    const unsigned fl5 = (unsigned)__ldg(&flags[341   + (int)(n9 >> 8)]);
    const unsigned fl4 = (unsigned)__ldg(&flags[85    + (int)(n9 >> 10)]);
    const unsigned fl3 = (unsigned)__ldg(&flags[21    + (int)(n9 >> 12)]);
    const unsigned fl2 = (unsigned)__ldg(&flags[5     + (int)(n9 >> 14)]);
    const unsigned fl1 = (unsigned)__ldg(&flags[1     + (int)(n9 >> 16)]);
    const unsigned fl0 = (unsigned)__ldg(&flags[0]);

    const float2 s01 = __ldg((const float2*)scale);
    const float2 o01 = __ldg((const float2*)offset);
    const float  s2  = __ldg(&scale[2]);
    const float  o2  = __ldg(&offset[2]);

    // ---- Build nibble LUT in registers ----
    const unsigned lane = threadIdx.x & 31u;
    const unsigned nib  = lane & 15u;
    const unsigned add  = (lane >> 4) & 1u;  // high nibble: rev3(b+4)=rev3(b)|1
    unsigned pk = 0, rank = 0;
    if (nib & 1u) { pk |= (0u + add) << (3u * rank); ++rank; }
    if (nib & 2u) { pk |= (4u + add) << (3u * rank); ++rank; }
    if (nib & 4u) { pk |= (2u + add) << (3u * rank); ++rank; }
    if (nib & 8u) { pk |= (6u + add) << (3u * rank);         }

    // ---- Decode: OR-tree of per-level 3-bit contributions ----
    const unsigned a0 = ((lut_lookup(pk, fl0) >> (3u * ((n9 >> 16) & 3u))) & 7u);
    const unsigned a1 = ((lut_lookup(pk, fl1) >> (3u * ((n9 >> 14) & 3u))) & 7u) << 3;
    const unsigned a2 = ((lut_lookup(pk, fl2) >> (3u * ((n9 >> 12) & 3u))) & 7u) << 6;
    const unsigned a3 = ((lut_lookup(pk, fl3) >> (3u * ((n9 >> 10) & 3u))) & 7u) << 9;
    const unsigned a4 = ((lut_lookup(pk, fl4) >> (3u * ((n9 >>  8) & 3u))) & 7u) << 12;
    const unsigned a5 = ((lut_lookup(pk, fl5) >> (3u * ((n9 >>  6) & 3u))) & 7u) << 15;
    const unsigned a6 = ((lut_lookup(pk, fl6) >> (3u * ((n9 >>  4) & 3u))) & 7u) << 18;
    const unsigned a7 = ((lut_lookup(pk, fl7) >> (3u * ((n9 >>  2) & 3u))) & 7u) << 21;
    const unsigned a8 = ((lut_lookup(pk, fl8) >> (3u * ( n9        & 3u))) & 7u) << 24;
    const unsigned p9 = lut_lookup(pk, fl9);        // all 4 leaf contributions

    const unsigned acc = ((a0 | a1) | (a2 | a3)) | ((a4 | a5) | (a6 | a7)) | a8;

    // c0, c1 shared by the 4 leaves; c2 varies only in its top 3 bits.
    const float v0    = (float)(acc & 1023u)         * s01.x + o01.x;
    const float v1    = (float)((acc >> 10) & 1023u) * s01.y + o01.y;
    const float fbase = (float)((acc >> 20) & 127u)  * s2 + o2;
    const float s2h   = s2 * 128.0f;

    const float vc0 = (float)( p9        & 7u) * s2h + fbase;
    const float vc1 = (float)((p9 >> 3)  & 7u) * s2h + fbase;
    const float vc2 = (float)((p9 >> 6)  & 7u) * s2h + fbase;
    const float vc3 = (float)((p9 >> 9)  & 7u) * s2h + fbase;

    // 12 consecutive floats (48B, 16B-aligned): 3 streaming STG.128.
    float4* o4 = reinterpret_cast<float4*>(out + (size_t)n9 * 12u);
    __stcs(o4 + 0, make_float4(v0,  v1,  vc0, v0));
    __stcs(o4 + 1, make_float4(v1,  vc1, v0,  v1));
    __stcs(o4 + 2, make_float4(vc2, v0,  v1,  vc3));
}

extern "C" void kernel_launch(void* const* d_in, const int* in_sizes, int n_in,
                              void* d_out, int out_size)
{
    const int*   flags  = (const int*)  d_in[0];
    const float* offset = (const float*)d_in[1];
    const float* scale  = (const float*)d_in[2];
    if (n_in == 3 && in_sizes[0] == 3) {   // defensive input-order handling
        int fi = (in_sizes[1] > 3) ? 1 : 2;
        flags = (const int*)d_in[fi];
        int s1 = -1, s2 = -1;
        for (int i = 0; i < 3; ++i) {
            if (i == fi) continue;
            if (s1 < 0) s1 = i; else s2 = i;
        }
        offset = (const float*)d_in[s1];
        scale  = (const float*)d_in[s2];
    }

    nbit_decode_kernel<<<NBLOCKS, BLOCK>>>(flags, offset, scale, (float*)d_out);
}